// round 1
// baseline (speedup 1.0000x reference)
#include <cuda_runtime.h>
#include <math.h>

// ----------------------------------------------------------------------------
// Net_52218212384916: x = 2*in-1; out1 = long_conv(x); out2 = long_conv(out1);
// return interp128(sigmoid(out2)).
// The looper branch is deterministically one iteration (lc_values==3.0) and
// does not affect the output values -> skipped.
// We only ever evaluate out1/out2 at the sparse positions actually consumed.
// ----------------------------------------------------------------------------

#define NIN 1024          // input H=W
#define HC1 510           // conv(1024) stride2 k5 VALID
#define HC2 1022          // conv(2047) stride2 k5 VALID
#define N1  2047          // out1 H=W
#define N2  4093          // out2 H=W

__device__ float g_key[2][3072];     // flattened sampled sigmoid(conv) keys
__device__ float g_dots[2][128];     // keys @ key
__device__ float g_kern[2][256];     // attention-mixed (3,3,5,5) kernels
__device__ float g_o1win[3 * 160 * 160]; // out1 values under key2's conv windows

__device__ __forceinline__ float sigf(float v) { return 1.f / (1.f + expf(-v)); }

// out1[oc, oh, ow] for all 3 oc at once. conv_transpose(x', kern, s=2, p=2, k=5):
//   out[oc,oh,ow] = sum_ic sum_{kh,kw} x'[ic,i,j] * kern[ic,oc,kh,kw],
//   with 2i = oh - 2 + (4-?) ... torch mapping: kh = oh - 2i + 2 in [0,5).
// x' = 2*x - 1 applied inline.
__device__ __forceinline__ void out1_val3(const float* __restrict__ x,
                                          const float* __restrict__ kk,
                                          int oh, int ow, float r[3]) {
    r[0] = 0.f; r[1] = 0.f; r[2] = 0.f;
#pragma unroll
    for (int kh = 0; kh < 5; ++kh) {
        int t = oh + 2 - kh;            // = 2i
        if (t & 1) continue;
        unsigned i = (unsigned)(t >> 1);
        if (i >= (unsigned)NIN) continue;
#pragma unroll
        for (int kw = 0; kw < 5; ++kw) {
            int u = ow + 2 - kw;
            if (u & 1) continue;
            unsigned j = (unsigned)(u >> 1);
            if (j >= (unsigned)NIN) continue;
            const float* xp = x + i * NIN + j;
            float x0 = 2.f * xp[0]             - 1.f;
            float x1 = 2.f * xp[NIN * NIN]     - 1.f;
            float x2 = 2.f * xp[2 * NIN * NIN] - 1.f;
            int ki = kh * 5 + kw;
#pragma unroll
            for (int oc = 0; oc < 3; ++oc)   // kern[ic,oc,kh,kw] = kk[ic*75+oc*25+ki]
                r[oc] += x0 * kk[oc * 25 + ki]
                       + x1 * kk[75  + oc * 25 + ki]
                       + x2 * kk[150 + oc * 25 + ki];
        }
    }
}

// Stage 1: key1[c*1024 + sr*32 + sc] = sigmoid(conv2d_s2(x', w, b)) at sampled pos.
__global__ void k_key1(const float* __restrict__ x, const float* __restrict__ w,
                       const float* __restrict__ b) {
    int tid = blockIdx.x * blockDim.x + threadIdx.x;
    if (tid >= 3072) return;
    int oc = tid >> 10, rem = tid & 1023;
    int sr = rem >> 5, sc = rem & 31;
    int r0 = 2 * ((sr * HC1) >> 5);      // conv input row of sampled conv output
    int c0 = 2 * ((sc * HC1) >> 5);
    float acc = b[oc];
#pragma unroll
    for (int ic = 0; ic < 3; ++ic) {
        const float* xp = x + ic * NIN * NIN + r0 * NIN + c0;
        const float* wp = w + oc * 75 + ic * 25;
#pragma unroll
        for (int kh = 0; kh < 5; ++kh)
#pragma unroll
            for (int kw = 0; kw < 5; ++kw)
                acc += (2.f * xp[kh * NIN + kw] - 1.f) * wp[kh * 5 + kw];
    }
    g_key[0][tid] = sigf(acc);
}

// dots[row] = keys[row] . key   (one block per row)
__global__ void k_dots(const float* __restrict__ keys, int stage) {
    int row = blockIdx.x;
    const float* kv = g_key[stage];
    const float* kr = keys + row * 3072;
    float p = 0.f;
    for (int k = threadIdx.x; k < 3072; k += blockDim.x)
        p += kr[k] * kv[k];
    __shared__ float sred[32];
#pragma unroll
    for (int o = 16; o; o >>= 1) p += __shfl_down_sync(0xffffffffu, p, o);
    if ((threadIdx.x & 31) == 0) sred[threadIdx.x >> 5] = p;
    __syncthreads();
    if (threadIdx.x == 0) {
        float s = 0.f;
        for (int i = 0; i < (int)blockDim.x / 32; ++i) s += sred[i];
        g_dots[stage][row] = s;
    }
}

// softmax over 100 dots, then kern[t] = sum_i att[i] * values[i, t]  (t < 225)
__global__ void k_combine(const float* __restrict__ values, int stage) {
    __shared__ float satt[100];
    __shared__ float sinv;
    int t = threadIdx.x;
    if (t < 100) satt[t] = g_dots[stage][t];
    __syncthreads();
    if (t == 0) {
        float m = satt[0];
        for (int i = 1; i < 100; ++i) m = fmaxf(m, satt[i]);
        float s = 0.f;
        for (int i = 0; i < 100; ++i) { float e = expf(satt[i] - m); satt[i] = e; s += e; }
        sinv = 1.f / s;
    }
    __syncthreads();
    if (t < 225) {
        float acc = 0.f;
        for (int i = 0; i < 100; ++i) acc += satt[i] * values[i * 225 + t];
        g_kern[stage][t] = acc * sinv;
    }
}

// out1 values under key2's sampled 5x5 conv windows: 160x160 positions, 3 ch.
__global__ void k_o1win(const float* __restrict__ x) {
    int tid = blockIdx.x * blockDim.x + threadIdx.x;
    if (tid >= 160 * 160) return;
    int rowi = tid / 160, coli = tid - rowi * 160;
    int sr = rowi / 5, kh = rowi - sr * 5;
    int sc = coli / 5, kw = coli - sc * 5;
    int oh = 2 * ((sr * HC2) >> 5) + kh;
    int ow = 2 * ((sc * HC2) >> 5) + kw;
    float r[3];
    out1_val3(x, g_kern[0], oh, ow, r);
    g_o1win[tid]             = r[0];
    g_o1win[25600 + tid]     = r[1];
    g_o1win[2 * 25600 + tid] = r[2];
}

// key2[c*1024 + sr*32 + sc] = sigmoid(conv2d_s2(out1, w, b)) at sampled pos.
__global__ void k_key2(const float* __restrict__ w, const float* __restrict__ b) {
    int tid = blockIdx.x * blockDim.x + threadIdx.x;
    if (tid >= 3072) return;
    int oc = tid >> 10, rem = tid & 1023;
    int sr = rem >> 5, sc = rem & 31;
    float acc = b[oc];
#pragma unroll
    for (int c1 = 0; c1 < 3; ++c1) {
        const float* sp = g_o1win + c1 * 25600 + (sr * 5) * 160 + sc * 5;
        const float* wp = w + oc * 75 + c1 * 25;
#pragma unroll
        for (int kh = 0; kh < 5; ++kh)
#pragma unroll
            for (int kw = 0; kw < 5; ++kw)
                acc += sp[kh * 160 + kw] * wp[kh * 5 + kw];
    }
    g_key[1][tid] = sigf(acc);
}

// Final: out[oc, r, c] = sigmoid(out2[oc, R, C]) at sampled (R, C),
// out2 = conv_transpose(out1, kern2); out1 taps recomputed from x on the fly.
__global__ void k_final(const float* __restrict__ x, float* __restrict__ out) {
    int tid = blockIdx.x * blockDim.x + threadIdx.x;
    if (tid >= 128 * 128) return;
    int r = tid >> 7, c = tid & 127;
    int R = (r * N2) >> 7;     // arange(128)*4093//128
    int C = (c * N2) >> 7;
    const float* k1 = g_kern[0];
    const float* k2 = g_kern[1];
    float a0 = 0.f, a1 = 0.f, a2 = 0.f;
#pragma unroll
    for (int kh = 0; kh < 5; ++kh) {
        int t = R + 2 - kh;
        if (t & 1) continue;
        unsigned i2 = (unsigned)(t >> 1);
        if (i2 >= (unsigned)N1) continue;
#pragma unroll
        for (int kw = 0; kw < 5; ++kw) {
            int u = C + 2 - kw;
            if (u & 1) continue;
            unsigned j2 = (unsigned)(u >> 1);
            if (j2 >= (unsigned)N1) continue;
            float ov[3];
            out1_val3(x, k1, (int)i2, (int)j2, ov);
            int ki = kh * 5 + kw;
            // kern2[c1, oc, kh, kw] = k2[c1*75 + oc*25 + ki]
            a0 += ov[0] * k2[ki]      + ov[1] * k2[75 + ki]  + ov[2] * k2[150 + ki];
            a1 += ov[0] * k2[25 + ki] + ov[1] * k2[100 + ki] + ov[2] * k2[175 + ki];
            a2 += ov[0] * k2[50 + ki] + ov[1] * k2[125 + ki] + ov[2] * k2[200 + ki];
        }
    }
    out[tid]                 = sigf(a0);
    out[16384 + tid]         = sigf(a1);
    out[2 * 16384 + tid]     = sigf(a2);
}

extern "C" void kernel_launch(void* const* d_in, const int* in_sizes, int n_in,
                              void* d_out, int out_size) {
    (void)in_sizes; (void)n_in; (void)out_size;
    const float* x      = (const float*)d_in[0];  // input [1,3,1024,1024]
    const float* w      = (const float*)d_in[1];  // lk1_conv_w [3,3,5,5]
    const float* b      = (const float*)d_in[2];  // lk1_conv_b [3]
    const float* keys   = (const float*)d_in[3];  // lk1_keys [100,3072]
    const float* values = (const float*)d_in[4];  // lk1_values [100,225]
    // d_in[5..8] (lc_*) only gate the loop, which is deterministically 1 iter.
    float* out = (float*)d_out;                   // [1,3,128,128] float32

    k_key1   <<<12,  256>>>(x, w, b);
    k_dots   <<<100, 128>>>(keys, 0);
    k_combine<<<1,   256>>>(values, 0);
    k_o1win  <<<100, 256>>>(x);
    k_key2   <<<12,  256>>>(w, b);
    k_dots   <<<100, 128>>>(keys, 1);
    k_combine<<<1,   256>>>(values, 1);
    k_final  <<<64,  256>>>(x, out);
}